// round 6
// baseline (speedup 1.0000x reference)
#include <cuda_runtime.h>
#include <math.h>

#define Bn 32
#define Cn 16
#define Hn 128
#define Wn 128
#define HW (Hn * Wn)
#define TW 64          // tile width
#define TH 32          // tile height; 2x4 = 8 tiles per image, 256 blocks
#define EXW 66         // extended (+-1)
#define EXH 34
#define SXW 68         // x tile (+-2)
#define SXH 36
#define EXN (EXH * EXW)   // 2244

// Border-ring exchange + per-image barrier counters.
__device__ float2 g_h[2][Bn * HW];
__device__ unsigned g_cnt[Bn];

typedef unsigned long long u64;

__device__ __forceinline__ u64 ffma2(u64 a, u64 b, u64 c) {
    u64 d;
    asm("fma.rn.f32x2 %0, %1, %2, %3;" : "=l"(d) : "l"(a), "l"(b), "l"(c));
    return d;
}
__device__ __forceinline__ u64 pack2(float v) {
    u64 r;
    asm("mov.b64 %0, {%1, %1};" : "=l"(r) : "f"(v));
    return r;
}
__device__ __forceinline__ u64 pack2f(float a, float b) {
    u64 r;
    asm("mov.b64 %0, {%1, %2};" : "=l"(r) : "f"(a), "f"(b));
    return r;
}
__device__ __forceinline__ void unpack2(u64 v, float& lo, float& hi) {
    asm("mov.b64 {%0, %1}, %2;" : "=f"(lo), "=f"(hi) : "l"(v));
}
__device__ __forceinline__ float tanh_fast(float x) {
    float y;
    asm("tanh.approx.f32 %0, %1;" : "=f"(y) : "f"(x));
    return y;
}
__device__ __forceinline__ float sigm(float v) {
    return fmaf(tanh_fast(0.5f * v), 0.5f, 0.5f);
}
__device__ __forceinline__ unsigned ld_acq(const unsigned* p) {
    unsigned v;
    asm volatile("ld.acquire.gpu.global.u32 %0, [%1];" : "=r"(v) : "l"(p));
    return v;
}

__device__ __forceinline__ float block_sum256(float v, float* sred) {
    #pragma unroll
    for (int o = 16; o > 0; o >>= 1) v += __shfl_down_sync(0xffffffffu, v, o);
    int lane = threadIdx.x & 31, wid = threadIdx.x >> 5;
    if (lane == 0) sred[wid] = v;
    __syncthreads();
    if (wid == 0) {
        v = (lane < 8) ? sred[lane] : 0.0f;
        #pragma unroll
        for (int o = 4; o > 0; o >>= 1) v += __shfl_down_sync(0xffffffffu, v, o);
    }
    return v;  // valid in thread 0
}

__global__ void zero_out_kernel(float* out) {
    if (threadIdx.x < Bn) { out[threadIdx.x] = 0.0f; g_cnt[threadIdx.x] = 0u; }
}

// Persistent fused ConvLSTM. Block = one 64x32 tile; 8 blocks per image sync
// via a per-image monotonic barrier. h state lives in smem (double-buffered);
// only the 1px border ring goes through global. All smem operands stored
// PRE-BROADCAST ({v,v} pairs) so FFMA2 inputs come straight from LDS.64/.128.
__global__ __launch_bounds__(256, 2) void lstm_kernel(
    const float* __restrict__ x,
    const float* __restrict__ Win,  const float* __restrict__ b_in,
    const float* __restrict__ Wih,  const float* __restrict__ b_ih,
    const float* __restrict__ Whh,  const float* __restrict__ b_hh,
    const float* __restrict__ Wout, const float* __restrict__ b_out,
    float* __restrict__ out)
{
    extern __shared__ __align__(16) float smem[];
    float* sWih  = smem;            // [72]
    float* sWhh  = smem + 72;       // [144]
    float* sWoutY= smem + 216;      // [36]
    float* sbias = smem + 252;      // [8]
    float* sWin  = smem + 260;      // [9]
    float* sbin  = smem + 269;
    float* sbout = smem + 270;      // [2]
    float* sred  = smem + 272;      // [16]
    float* sx    = smem + 288;      // [36*68] x, offset (-2,-2)
    float* szi2  = smem + 2736;     // [EXN][2]  {zi,zi}
    float* sh4   = smem + 5120;     // [2][EXN][4] {h0,h0,h1,h1}

    const int tid = threadIdx.x;
    const int b = blockIdx.z;
    const int gx0 = blockIdx.x * TW, gy0 = blockIdx.y * TH;
    const int ix = tid & 63;                 // column within tile
    const int yg = (tid >> 6) << 3;          // first of 8 rows handled

    // ---- weights -> smem (once) ----
    if (tid < 144) sWhh[tid] = Whh[tid];
    if (tid < 72)  sWih[tid] = Wih[tid];
    if (tid < 36) {  // Wout_y = Wout[:,:,:2,:], src flat (k*4+ci)*2+co
        int k = tid >> 2, ci = (tid >> 1) & 1, co = tid & 1;
        sWoutY[tid] = Wout[(k * 4 + ci) * 2 + co];
    }
    if (tid < 9) sWin[tid] = Win[tid];
    if (tid < 8) sbias[tid] = b_ih[tid] + b_hh[tid];
    if (tid < 2) sbout[tid] = b_out[tid];
    if (tid == 0) sbin[0] = b_in[0];
    for (int i = tid; i < 8 * EXN; i += 256) sh4[i] = 0.0f;   // h_0 = 0

    float c0[8], c1[8];
    #pragma unroll
    for (int k = 0; k < 8; k++) { c0[k] = 0.0f; c1[k] = 0.0f; }

    // ---- prologue: x(0), zi(0), channel-0 log-prob ----
    {
        const float* xin = x + (size_t)(b * Cn) * HW;
        for (int i = tid; i < SXH * SXW; i += 256) {
            int r = i / SXW, c = i - r * SXW;
            int gy = gy0 - 2 + r, gx = gx0 - 2 + c;
            float v = 0.0f;
            if ((unsigned)gy < Hn && (unsigned)gx < Wn) v = xin[gy * Wn + gx];
            sx[i] = v;
        }
    }
    __syncthreads();

    const u64* w1p = (const u64*)sWih;
    const u64* w2p = (const u64*)sWhh;
    const u64* wop = (const u64*)sWoutY;
    const u64* sbp = (const u64*)sbias;
    const u64 pbias = pack2f(sbout[0], sbout[1]);

    float lpacc = 0.0f;
    {
        float mu = sbout[0], ls = sbout[1];
        float e = __expf(-ls);
        #pragma unroll
        for (int k = 0; k < 8; k++) {
            float xv = sx[(yg + k + 2) * SXW + ix + 2];
            float z = (xv - mu) * e;
            lpacc += -0.5f * z * z - ls - 0.9189385332046727f;
        }
    }
    {
        float bin = sbin[0];
        for (int i = tid; i < EXN; i += 256) {
            int r = i / EXW, c = i - r * EXW;
            int gy = gy0 - 1 + r, gx = gx0 - 1 + c;
            float v = 0.0f;
            if ((unsigned)gy < Hn && (unsigned)gx < Wn) {
                v = bin;
                #pragma unroll
                for (int dy = 0; dy < 3; dy++)
                    #pragma unroll
                    for (int dx = 0; dx < 3; dx++)
                        v += sx[(r + dy) * SXW + (c + dx)] * sWin[dy * 3 + dx];
            }
            *(u64*)(szi2 + i * 2) = pack2(v);
        }
    }
    __syncthreads();

    for (int t = 0; t < 15; t++) {
        const int cur = t & 1, nxt = cur ^ 1;
        float* shc = sh4 + cur * 4 * EXN;
        float* shn = sh4 + nxt * 4 * EXN;
        float2* ghp = g_h[nxt] + (size_t)b * HW;

        // (1) gates + LSTM, interior, tap-outer in 2 passes of 4 rows.
        #pragma unroll
        for (int p = 0; p < 2; p++) {
            u64 acc[4][4];
            #pragma unroll
            for (int j = 0; j < 4; j++) {
                acc[j][0] = sbp[0]; acc[j][1] = sbp[1];
                acc[j][2] = sbp[2]; acc[j][3] = sbp[3];
            }
            #pragma unroll
            for (int tap = 0; tap < 9; tap++) {
                const int dy = tap / 3, dx = tap % 3;
                u64 wz0 = w1p[tap * 4 + 0], wz1 = w1p[tap * 4 + 1];
                u64 wz2 = w1p[tap * 4 + 2], wz3 = w1p[tap * 4 + 3];
                u64 wa0 = w2p[tap * 8 + 0], wa1 = w2p[tap * 8 + 1];
                u64 wa2 = w2p[tap * 8 + 2], wa3 = w2p[tap * 8 + 3];
                u64 wb0 = w2p[tap * 8 + 4], wb1 = w2p[tap * 8 + 5];
                u64 wb2 = w2p[tap * 8 + 6], wb3 = w2p[tap * 8 + 7];
                #pragma unroll
                for (int j = 0; j < 4; j++) {
                    int si = (yg + p * 4 + j + dy) * EXW + ix + dx;
                    u64 zp = *(const u64*)(szi2 + si * 2);       // (zi,zi)
                    ulonglong2 hq = *(const ulonglong2*)(shc + si * 4);
                    acc[j][0] = ffma2(zp,   wz0, acc[j][0]);
                    acc[j][1] = ffma2(zp,   wz1, acc[j][1]);
                    acc[j][2] = ffma2(zp,   wz2, acc[j][2]);
                    acc[j][3] = ffma2(zp,   wz3, acc[j][3]);
                    acc[j][0] = ffma2(hq.x, wa0, acc[j][0]);
                    acc[j][1] = ffma2(hq.x, wa1, acc[j][1]);
                    acc[j][2] = ffma2(hq.x, wa2, acc[j][2]);
                    acc[j][3] = ffma2(hq.x, wa3, acc[j][3]);
                    acc[j][0] = ffma2(hq.y, wb0, acc[j][0]);
                    acc[j][1] = ffma2(hq.y, wb1, acc[j][1]);
                    acc[j][2] = ffma2(hq.y, wb2, acc[j][2]);
                    acc[j][3] = ffma2(hq.y, wb3, acc[j][3]);
                }
            }
            #pragma unroll
            for (int j = 0; j < 4; j++) {
                const int k = p * 4 + j;
                int R = yg + k;
                float i0, i1, g0, g1, f0, f1, o0, o1;
                unpack2(acc[j][0], i0, i1); unpack2(acc[j][1], g0, g1);
                unpack2(acc[j][2], f0, f1); unpack2(acc[j][3], o0, o1);
                float cn0 = sigm(f0 + 1.0f) * c0[k] + sigm(i0) * tanh_fast(g0);
                float cn1 = sigm(f1 + 1.0f) * c1[k] + sigm(i1) * tanh_fast(g1);
                c0[k] = cn0; c1[k] = cn1;
                float hn0 = sigm(o0) * tanh_fast(cn0);
                float hn1 = sigm(o1) * tanh_fast(cn1);
                int ei = (R + 1) * EXW + ix + 1;
                ulonglong2 hv; hv.x = pack2(hn0); hv.y = pack2(hn1);
                *(ulonglong2*)(shn + ei * 4) = hv;
                if (R == 0 || R == TH - 1 || ix == 0 || ix == TW - 1)
                    ghp[(gy0 + R) * Wn + gx0 + ix] = make_float2(hn0, hn1);
            }
        }
        __syncthreads();
        // (2) arrive on per-image barrier
        if (tid == 0) { __threadfence(); atomicAdd(&g_cnt[b], 1u); }

        // (3) load x(t+1) (hides barrier latency)
        {
            const float* xin = x + (size_t)(b * Cn + t + 1) * HW;
            for (int i = tid; i < SXH * SXW; i += 256) {
                int r = i / SXW, c = i - r * SXW;
                int gy = gy0 - 2 + r, gx = gx0 - 2 + c;
                float v = 0.0f;
                if ((unsigned)gy < Hn && (unsigned)gx < Wn) v = xin[gy * Wn + gx];
                sx[i] = v;
            }
        }
        __syncthreads();
        // (4) zi(t+1) (also hides barrier latency; zi(t) fully consumed above)
        if (t < 14) {
            float bin = sbin[0];
            for (int i = tid; i < EXN; i += 256) {
                int r = i / EXW, c = i - r * EXW;
                int gy = gy0 - 1 + r, gx = gx0 - 1 + c;
                float v = 0.0f;
                if ((unsigned)gy < Hn && (unsigned)gx < Wn) {
                    v = bin;
                    #pragma unroll
                    for (int dy = 0; dy < 3; dy++)
                        #pragma unroll
                        for (int dx = 0; dx < 3; dx++)
                            v += sx[(r + dy) * SXW + (c + dx)] * sWin[dy * 3 + dx];
                }
                *(u64*)(szi2 + i * 2) = pack2(v);
            }
        }
        // (5) wait for the other 7 blocks of this image
        if (tid == 0) {
            unsigned target = 8u * (unsigned)(t + 1);
            while (ld_acq(&g_cnt[b]) < target) { __nanosleep(64); }
        }
        __syncthreads();
        // (6) pull the halo ring of h(t+1) (bypass L1)
        if (tid < 196) {
            int rr, cc;
            if (tid < 66)        { rr = 0;               cc = tid; }
            else if (tid < 132)  { rr = EXH - 1;         cc = tid - 66; }
            else if (tid < 164)  { rr = 1 + (tid - 132); cc = 0; }
            else                 { rr = 1 + (tid - 164); cc = EXW - 1; }
            int gy = gy0 - 1 + rr, gx = gx0 - 1 + cc;
            float2 hv = make_float2(0.0f, 0.0f);
            if ((unsigned)gy < Hn && (unsigned)gx < Wn)
                hv = __ldcg(&ghp[gy * Wn + gx]);
            ulonglong2 hq; hq.x = pack2(hv.x); hq.y = pack2(hv.y);
            *(ulonglong2*)(shn + (rr * EXW + cc) * 4) = hq;
        }
        __syncthreads();
        // (7) out conv over h(t+1); log-prob vs x(t+1) (in sx)
        #pragma unroll
        for (int k = 0; k < 8; k++) {
            int R = yg + k;
            u64 pp = pbias;
            #pragma unroll
            for (int tap = 0; tap < 9; tap++) {
                const int dy = tap / 3, dx = tap % 3;
                int si = (R + dy) * EXW + ix + dx;
                ulonglong2 hq = *(const ulonglong2*)(shn + si * 4);
                pp = ffma2(hq.x, wop[tap * 2 + 0], pp);
                pp = ffma2(hq.y, wop[tap * 2 + 1], pp);
            }
            float p0, p1;
            unpack2(pp, p0, p1);
            float xv = sx[(R + 2) * SXW + ix + 2];
            float e = __expf(-p1);
            float z = (xv - p0) * e;
            lpacc += -0.5f * z * z - p1 - 0.9189385332046727f;
        }
    }

    float tot = block_sum256(lpacc, sred);
    if (tid == 0) atomicAdd(&out[b], tot);
}

extern "C" void kernel_launch(void* const* d_in, const int* in_sizes, int n_in,
                              void* d_out, int out_size) {
    const float* x     = (const float*)d_in[0];
    const float* Win   = (const float*)d_in[1];
    const float* b_in  = (const float*)d_in[2];
    const float* Wih   = (const float*)d_in[3];
    const float* b_ih  = (const float*)d_in[4];
    const float* Whh   = (const float*)d_in[5];
    const float* b_hh  = (const float*)d_in[6];
    const float* Wout  = (const float*)d_in[7];
    const float* b_out = (const float*)d_in[8];
    float* out = (float*)d_out;

    static int smem_set = 0;
    const int smem_bytes = (5120 + 8 * EXN) * 4;   // 92288 B... (5120 + 17952)*4
    if (!smem_set) {
        cudaFuncSetAttribute(lstm_kernel,
                             cudaFuncAttributeMaxDynamicSharedMemorySize,
                             smem_bytes);
        smem_set = 1;
    }

    zero_out_kernel<<<1, 32>>>(out);

    dim3 grid(Wn / TW, Hn / TH, Bn);   // 2 x 4 x 32 = 256 blocks, 2 per SM
    lstm_kernel<<<grid, 256, smem_bytes>>>(x, Win, b_in, Wih, b_ih, Whh, b_hh,
                                           Wout, b_out, out);
}

// round 7
// speedup vs baseline: 1.0814x; 1.0814x over previous
#include <cuda_runtime.h>
#include <math.h>

#define Bn 32
#define Cn 16
#define Hn 128
#define Wn 128
#define HW (Hn * Wn)
#define TW 64          // tile width
#define TH 32          // tile height; 2x4 = 8 tiles per image, 256 blocks
#define EXW 66         // extended (+-1)
#define EXH 34
#define SXW 68         // x tile (+-2)
#define SXH 36
#define EXN (EXH * EXW)   // 2244

// Border-ring exchange + per-image barrier counters.
__device__ float2 g_h[2][Bn * HW];
__device__ unsigned g_cnt[Bn];

typedef unsigned long long u64;

__device__ __forceinline__ u64 ffma2(u64 a, u64 b, u64 c) {
    u64 d;
    asm("fma.rn.f32x2 %0, %1, %2, %3;" : "=l"(d) : "l"(a), "l"(b), "l"(c));
    return d;
}
__device__ __forceinline__ u64 pack2(float v) {
    u64 r;
    asm("mov.b64 %0, {%1, %1};" : "=l"(r) : "f"(v));
    return r;
}
__device__ __forceinline__ u64 pack2f(float a, float b) {
    u64 r;
    asm("mov.b64 %0, {%1, %2};" : "=l"(r) : "f"(a), "f"(b));
    return r;
}
__device__ __forceinline__ void unpack2(u64 v, float& lo, float& hi) {
    asm("mov.b64 {%0, %1}, %2;" : "=f"(lo), "=f"(hi) : "l"(v));
}
__device__ __forceinline__ float tanh_fast(float x) {
    float y;
    asm("tanh.approx.f32 %0, %1;" : "=f"(y) : "f"(x));
    return y;
}
__device__ __forceinline__ float sigm(float v) {
    return fmaf(tanh_fast(0.5f * v), 0.5f, 0.5f);
}
__device__ __forceinline__ unsigned ld_acq(const unsigned* p) {
    unsigned v;
    asm volatile("ld.acquire.gpu.global.u32 %0, [%1];" : "=r"(v) : "l"(p));
    return v;
}

__device__ __forceinline__ float block_sum256(float v, float* sred) {
    #pragma unroll
    for (int o = 16; o > 0; o >>= 1) v += __shfl_down_sync(0xffffffffu, v, o);
    int lane = threadIdx.x & 31, wid = threadIdx.x >> 5;
    if (lane == 0) sred[wid] = v;
    __syncthreads();
    if (wid == 0) {
        v = (lane < 8) ? sred[lane] : 0.0f;
        #pragma unroll
        for (int o = 4; o > 0; o >>= 1) v += __shfl_down_sync(0xffffffffu, v, o);
    }
    return v;  // valid in thread 0
}

__global__ void zero_out_kernel(float* out) {
    if (threadIdx.x < Bn) { out[threadIdx.x] = 0.0f; g_cnt[threadIdx.x] = 0u; }
}

// Persistent fused ConvLSTM. Block = one 64x32 tile; 8 blocks per image sync
// via a per-image monotonic barrier. h state lives in smem (double-buffered);
// only the 1px border ring goes through global. Out-conv is split: interior
// pixels (no ring dependency) are computed BEFORE the barrier wait, so only
// ~190 border px/block remain on the post-barrier critical path.
__global__ __launch_bounds__(256, 2) void lstm_kernel(
    const float* __restrict__ x,
    const float* __restrict__ Win,  const float* __restrict__ b_in,
    const float* __restrict__ Wih,  const float* __restrict__ b_ih,
    const float* __restrict__ Whh,  const float* __restrict__ b_hh,
    const float* __restrict__ Wout, const float* __restrict__ b_out,
    float* __restrict__ out)
{
    extern __shared__ __align__(16) float smem[];
    float* sWih  = smem;            // [72]
    float* sWhh  = smem + 72;       // [144]
    float* sWoutY= smem + 216;      // [36]
    float* sbias = smem + 252;      // [8]
    float* sWin  = smem + 260;      // [9]
    float* sbin  = smem + 269;
    float* sbout = smem + 270;      // [2]
    float* sred  = smem + 272;      // [16]
    float* sx    = smem + 288;      // [36*68] x, offset (-2,-2)
    float* szi   = smem + 2736;     // [34*66] zi, offset (-1,-1)
    float* shp   = smem + 4980;     // [2][2][34*66] h: [buf][ch]

    const int tid = threadIdx.x;
    const int b = blockIdx.z;
    const int gx0 = blockIdx.x * TW, gy0 = blockIdx.y * TH;
    const int ix = tid & 63;                 // column within tile
    const int yg = (tid >> 6) << 3;          // first of 8 rows handled

    // ---- weights -> smem (once) ----
    if (tid < 144) sWhh[tid] = Whh[tid];
    if (tid < 72)  sWih[tid] = Wih[tid];
    if (tid < 36) {  // Wout_y = Wout[:,:,:2,:], src flat (k*4+ci)*2+co
        int k = tid >> 2, ci = (tid >> 1) & 1, co = tid & 1;
        sWoutY[tid] = Wout[(k * 4 + ci) * 2 + co];
    }
    if (tid < 9) sWin[tid] = Win[tid];
    if (tid < 8) sbias[tid] = b_ih[tid] + b_hh[tid];
    if (tid < 2) sbout[tid] = b_out[tid];
    if (tid == 0) sbin[0] = b_in[0];
    for (int i = tid; i < 4 * EXN; i += 256) shp[i] = 0.0f;   // h_0 = 0

    float c0[8], c1[8];
    #pragma unroll
    for (int k = 0; k < 8; k++) { c0[k] = 0.0f; c1[k] = 0.0f; }

    // ---- prologue: x(0), zi(0), channel-0 log-prob ----
    {
        const float* xin = x + (size_t)(b * Cn) * HW;
        for (int i = tid; i < SXH * SXW; i += 256) {
            int r = i / SXW, c = i - r * SXW;
            int gy = gy0 - 2 + r, gx = gx0 - 2 + c;
            float v = 0.0f;
            if ((unsigned)gy < Hn && (unsigned)gx < Wn) v = xin[gy * Wn + gx];
            sx[i] = v;
        }
    }
    __syncthreads();

    const u64* w1p = (const u64*)sWih;
    const u64* w2p = (const u64*)sWhh;
    const u64* wop = (const u64*)sWoutY;
    const u64* sbp = (const u64*)sbias;
    const u64 pbias = pack2f(sbout[0], sbout[1]);

    float lpacc = 0.0f;
    {
        float mu = sbout[0], ls = sbout[1];
        float e = __expf(-ls);
        #pragma unroll
        for (int k = 0; k < 8; k++) {
            float xv = sx[(yg + k + 2) * SXW + ix + 2];
            float z = (xv - mu) * e;
            lpacc += -0.5f * z * z - ls - 0.9189385332046727f;
        }
    }
    {
        float bin = sbin[0];
        for (int i = tid; i < EXN; i += 256) {
            int r = i / EXW, c = i - r * EXW;
            int gy = gy0 - 1 + r, gx = gx0 - 1 + c;
            float v = 0.0f;
            if ((unsigned)gy < Hn && (unsigned)gx < Wn) {
                v = bin;
                #pragma unroll
                for (int dy = 0; dy < 3; dy++)
                    #pragma unroll
                    for (int dx = 0; dx < 3; dx++)
                        v += sx[(r + dy) * SXW + (c + dx)] * sWin[dy * 3 + dx];
            }
            szi[i] = v;
        }
    }
    __syncthreads();

    for (int t = 0; t < 15; t++) {
        const int cur = t & 1, nxt = cur ^ 1;
        float* sh0  = shp + cur * 2 * EXN;
        float* sh1  = sh0 + EXN;
        float* shn0 = shp + nxt * 2 * EXN;
        float* shn1 = shn0 + EXN;
        float2* ghp = g_h[nxt] + (size_t)b * HW;

        // (1) gates + LSTM, interior, tap-outer in 2 passes of 4 rows.
        #pragma unroll
        for (int p = 0; p < 2; p++) {
            u64 acc[4][4];
            #pragma unroll
            for (int j = 0; j < 4; j++) {
                acc[j][0] = sbp[0]; acc[j][1] = sbp[1];
                acc[j][2] = sbp[2]; acc[j][3] = sbp[3];
            }
            #pragma unroll
            for (int tap = 0; tap < 9; tap++) {
                const int dy = tap / 3, dx = tap % 3;
                u64 wz0 = w1p[tap * 4 + 0], wz1 = w1p[tap * 4 + 1];
                u64 wz2 = w1p[tap * 4 + 2], wz3 = w1p[tap * 4 + 3];
                u64 wa0 = w2p[tap * 8 + 0], wa1 = w2p[tap * 8 + 1];
                u64 wa2 = w2p[tap * 8 + 2], wa3 = w2p[tap * 8 + 3];
                u64 wb0 = w2p[tap * 8 + 4], wb1 = w2p[tap * 8 + 5];
                u64 wb2 = w2p[tap * 8 + 6], wb3 = w2p[tap * 8 + 7];
                #pragma unroll
                for (int j = 0; j < 4; j++) {
                    int si = (yg + p * 4 + j + dy) * EXW + ix + dx;
                    u64 zp  = pack2(szi[si]);
                    u64 h0p = pack2(sh0[si]);
                    u64 h1p = pack2(sh1[si]);
                    acc[j][0] = ffma2(zp,  wz0, acc[j][0]);
                    acc[j][1] = ffma2(zp,  wz1, acc[j][1]);
                    acc[j][2] = ffma2(zp,  wz2, acc[j][2]);
                    acc[j][3] = ffma2(zp,  wz3, acc[j][3]);
                    acc[j][0] = ffma2(h0p, wa0, acc[j][0]);
                    acc[j][1] = ffma2(h0p, wa1, acc[j][1]);
                    acc[j][2] = ffma2(h0p, wa2, acc[j][2]);
                    acc[j][3] = ffma2(h0p, wa3, acc[j][3]);
                    acc[j][0] = ffma2(h1p, wb0, acc[j][0]);
                    acc[j][1] = ffma2(h1p, wb1, acc[j][1]);
                    acc[j][2] = ffma2(h1p, wb2, acc[j][2]);
                    acc[j][3] = ffma2(h1p, wb3, acc[j][3]);
                }
            }
            #pragma unroll
            for (int j = 0; j < 4; j++) {
                const int k = p * 4 + j;
                int R = yg + k;
                float i0, i1, g0, g1, f0, f1, o0, o1;
                unpack2(acc[j][0], i0, i1); unpack2(acc[j][1], g0, g1);
                unpack2(acc[j][2], f0, f1); unpack2(acc[j][3], o0, o1);
                float cn0 = sigm(f0 + 1.0f) * c0[k] + sigm(i0) * tanh_fast(g0);
                float cn1 = sigm(f1 + 1.0f) * c1[k] + sigm(i1) * tanh_fast(g1);
                c0[k] = cn0; c1[k] = cn1;
                float hn0 = sigm(o0) * tanh_fast(cn0);
                float hn1 = sigm(o1) * tanh_fast(cn1);
                int ei = (R + 1) * EXW + ix + 1;
                shn0[ei] = hn0; shn1[ei] = hn1;
                if (R == 0 || R == TH - 1 || ix == 0 || ix == TW - 1)
                    ghp[(gy0 + R) * Wn + gx0 + ix] = make_float2(hn0, hn1);
            }
        }
        __syncthreads();
        // (2) arrive on per-image barrier (ring STGs ordered before it)
        if (tid == 0) { __threadfence(); atomicAdd(&g_cnt[b], 1u); }

        // (3) load x(t+1) (hides barrier skew)
        {
            const float* xin = x + (size_t)(b * Cn + t + 1) * HW;
            for (int i = tid; i < SXH * SXW; i += 256) {
                int r = i / SXW, c = i - r * SXW;
                int gy = gy0 - 2 + r, gx = gx0 - 2 + c;
                float v = 0.0f;
                if ((unsigned)gy < Hn && (unsigned)gx < Wn) v = xin[gy * Wn + gx];
                sx[i] = v;
            }
        }
        __syncthreads();
        // (4) zi(t+1) (hides barrier skew; zi(t) fully consumed in phase 1)
        if (t < 14) {
            float bin = sbin[0];
            for (int i = tid; i < EXN; i += 256) {
                int r = i / EXW, c = i - r * EXW;
                int gy = gy0 - 1 + r, gx = gx0 - 1 + c;
                float v = 0.0f;
                if ((unsigned)gy < Hn && (unsigned)gx < Wn) {
                    v = bin;
                    #pragma unroll
                    for (int dy = 0; dy < 3; dy++)
                        #pragma unroll
                        for (int dx = 0; dx < 3; dx++)
                            v += sx[(r + dy) * SXW + (c + dx)] * sWin[dy * 3 + dx];
                }
                szi[i] = v;
            }
        }
        // (5) out conv for INTERIOR pixels (no ring needed) with vertical
        //     register reuse: each loaded h-pair feeds 3 row-accumulators.
        {
            u64 pp[8];
            #pragma unroll
            for (int k = 0; k < 8; k++) pp[k] = pbias;
            #pragma unroll
            for (int dx = 0; dx < 3; dx++) {
                u64 w00 = wop[(0 * 3 + dx) * 2 + 0], w01 = wop[(0 * 3 + dx) * 2 + 1];
                u64 w10 = wop[(1 * 3 + dx) * 2 + 0], w11 = wop[(1 * 3 + dx) * 2 + 1];
                u64 w20 = wop[(2 * 3 + dx) * 2 + 0], w21 = wop[(2 * 3 + dx) * 2 + 1];
                #pragma unroll
                for (int rr = 0; rr < 10; rr++) {
                    int si = (yg + rr) * EXW + ix + dx;
                    u64 h0 = pack2(shn0[si]);
                    u64 h1 = pack2(shn1[si]);
                    if (rr < 8) {
                        pp[rr] = ffma2(h0, w00, pp[rr]);
                        pp[rr] = ffma2(h1, w01, pp[rr]);
                    }
                    if (rr >= 1 && rr < 9) {
                        pp[rr - 1] = ffma2(h0, w10, pp[rr - 1]);
                        pp[rr - 1] = ffma2(h1, w11, pp[rr - 1]);
                    }
                    if (rr >= 2) {
                        pp[rr - 2] = ffma2(h0, w20, pp[rr - 2]);
                        pp[rr - 2] = ffma2(h1, w21, pp[rr - 2]);
                    }
                }
            }
            if (ix >= 1 && ix <= 62) {
                #pragma unroll
                for (int k = 0; k < 8; k++) {
                    int R = yg + k;
                    if (R >= 1 && R <= 30) {
                        float p0, p1;
                        unpack2(pp[k], p0, p1);
                        float xv = sx[(R + 2) * SXW + ix + 2];
                        float e = __expf(-p1);
                        float z = (xv - p0) * e;
                        lpacc += -0.5f * z * z - p1 - 0.9189385332046727f;
                    }
                }
            }
        }
        // (6) wait for the other 7 blocks of this image
        if (tid == 0) {
            unsigned target = 8u * (unsigned)(t + 1);
            while (ld_acq(&g_cnt[b]) < target) { __nanosleep(64); }
        }
        __syncthreads();
        // (7) pull the halo ring of h(t+1) (bypass L1)
        if (tid < 196) {
            int rr, cc;
            if (tid < 66)        { rr = 0;               cc = tid; }
            else if (tid < 132)  { rr = EXH - 1;         cc = tid - 66; }
            else if (tid < 164)  { rr = 1 + (tid - 132); cc = 0; }
            else                 { rr = 1 + (tid - 164); cc = EXW - 1; }
            int gy = gy0 - 1 + rr, gx = gx0 - 1 + cc;
            float2 hv = make_float2(0.0f, 0.0f);
            if ((unsigned)gy < Hn && (unsigned)gx < Wn)
                hv = __ldcg(&ghp[gy * Wn + gx]);
            shn0[rr * EXW + cc] = hv.x;
            shn1[rr * EXW + cc] = hv.y;
        }
        __syncthreads();
        // (8) out conv for BORDER pixels only (now ring is valid)
        #pragma unroll
        for (int k = 0; k < 8; k++) {
            int R = yg + k;
            if (R == 0 || R == TH - 1 || ix == 0 || ix == TW - 1) {
                u64 pp = pbias;
                #pragma unroll
                for (int tap = 0; tap < 9; tap++) {
                    const int dy = tap / 3, dx = tap % 3;
                    int si = (R + dy) * EXW + ix + dx;
                    pp = ffma2(pack2(shn0[si]), wop[tap * 2 + 0], pp);
                    pp = ffma2(pack2(shn1[si]), wop[tap * 2 + 1], pp);
                }
                float p0, p1;
                unpack2(pp, p0, p1);
                float xv = sx[(R + 2) * SXW + ix + 2];
                float e = __expf(-p1);
                float z = (xv - p0) * e;
                lpacc += -0.5f * z * z - p1 - 0.9189385332046727f;
            }
        }
        // no extra sync: next iteration's first write to shn-ring happens
        // after its own phase-(7) barrier; gate phase reads shn (as shc)
        // which is stable from here.
    }

    float tot = block_sum256(lpacc, sred);
    if (tid == 0) atomicAdd(&out[b], tot);
}

extern "C" void kernel_launch(void* const* d_in, const int* in_sizes, int n_in,
                              void* d_out, int out_size) {
    const float* x     = (const float*)d_in[0];
    const float* Win   = (const float*)d_in[1];
    const float* b_in  = (const float*)d_in[2];
    const float* Wih   = (const float*)d_in[3];
    const float* b_ih  = (const float*)d_in[4];
    const float* Whh   = (const float*)d_in[5];
    const float* b_hh  = (const float*)d_in[6];
    const float* Wout  = (const float*)d_in[7];
    const float* b_out = (const float*)d_in[8];
    float* out = (float*)d_out;

    static int smem_set = 0;
    const int smem_bytes = (4980 + 4 * EXN) * 4;   // 55824 B
    if (!smem_set) {
        cudaFuncSetAttribute(lstm_kernel,
                             cudaFuncAttributeMaxDynamicSharedMemorySize,
                             smem_bytes);
        smem_set = 1;
    }

    zero_out_kernel<<<1, 32>>>(out);

    dim3 grid(Wn / TW, Hn / TH, Bn);   // 2 x 4 x 32 = 256 blocks, 2 per SM
    lstm_kernel<<<grid, 256, smem_bytes>>>(x, Win, b_in, Wih, b_ih, Whh, b_hh,
                                           Wout, b_out, out);
}

// round 8
// speedup vs baseline: 1.9981x; 1.8477x over previous
#include <cuda_runtime.h>
#include <math.h>

#define Bn 32
#define Cn 16
#define Hn 128
#define Wn 128
#define HW (Hn * Wn)
#define TW 64          // tile width
#define TH 32          // tile height; 2x4 = 8 tiles per image = one cluster
#define EXW 66         // extended (+-1)
#define EXH 34
#define SXW 68         // x tile (+-2)
#define SXH 36
#define EXN (EXH * EXW)   // 2244

typedef unsigned long long u64;

__device__ __forceinline__ u64 ffma2(u64 a, u64 b, u64 c) {
    u64 d;
    asm("fma.rn.f32x2 %0, %1, %2, %3;" : "=l"(d) : "l"(a), "l"(b), "l"(c));
    return d;
}
__device__ __forceinline__ u64 pack2(float v) {
    u64 r;
    asm("mov.b64 %0, {%1, %1};" : "=l"(r) : "f"(v));
    return r;
}
__device__ __forceinline__ u64 pack2f(float a, float b) {
    u64 r;
    asm("mov.b64 %0, {%1, %2};" : "=l"(r) : "f"(a), "f"(b));
    return r;
}
__device__ __forceinline__ void unpack2(u64 v, float& lo, float& hi) {
    asm("mov.b64 {%0, %1}, %2;" : "=f"(lo), "=f"(hi) : "l"(v));
}
__device__ __forceinline__ float tanh_fast(float x) {
    float y;
    asm("tanh.approx.f32 %0, %1;" : "=f"(y) : "f"(x));
    return y;
}
__device__ __forceinline__ float sigm(float v) {
    return fmaf(tanh_fast(0.5f * v), 0.5f, 0.5f);
}
__device__ __forceinline__ unsigned smem_u32(const void* p) {
    unsigned a;
    asm("{ .reg .u64 t; cvta.to.shared.u64 t, %1; cvt.u32.u64 %0, t; }"
        : "=r"(a) : "l"(p));
    return a;
}
__device__ __forceinline__ unsigned mapa32(unsigned addr, unsigned rank) {
    unsigned r;
    asm("mapa.shared::cluster.u32 %0, %1, %2;" : "=r"(r) : "r"(addr), "r"(rank));
    return r;
}
__device__ __forceinline__ void st_cluster(unsigned addr, float v) {
    asm volatile("st.shared::cluster.f32 [%0], %1;" :: "r"(addr), "f"(v) : "memory");
}

__device__ __forceinline__ float block_sum256(float v, float* sred) {
    #pragma unroll
    for (int o = 16; o > 0; o >>= 1) v += __shfl_down_sync(0xffffffffu, v, o);
    int lane = threadIdx.x & 31, wid = threadIdx.x >> 5;
    if (lane == 0) sred[wid] = v;
    __syncthreads();
    if (wid == 0) {
        v = (lane < 8) ? sred[lane] : 0.0f;
        #pragma unroll
        for (int o = 4; o > 0; o >>= 1) v += __shfl_down_sync(0xffffffffu, v, o);
    }
    return v;  // valid in thread 0
}

__global__ void zero_out_kernel(float* out) {
    if (threadIdx.x < Bn) out[threadIdx.x] = 0.0f;
}

// Persistent fused ConvLSTM. Cluster (8 CTAs) = one image, CTA = 64x32 tile.
// h state lives in smem (double-buffered). Border h pixels are pushed straight
// into neighbors' smem halos via st.shared::cluster; the per-step sync is a
// split cluster barrier (arrive after gates, wait before halo reads), with
// x(t+1) load + zi(t+1) hiding the skew.
__global__ __launch_bounds__(256, 2) __cluster_dims__(8, 1, 1)
void lstm_kernel(
    const float* __restrict__ x,
    const float* __restrict__ Win,  const float* __restrict__ b_in,
    const float* __restrict__ Wih,  const float* __restrict__ b_ih,
    const float* __restrict__ Whh,  const float* __restrict__ b_hh,
    const float* __restrict__ Wout, const float* __restrict__ b_out,
    float* __restrict__ out)
{
    extern __shared__ __align__(16) float smem[];
    float* sWih  = smem;            // [72]
    float* sWhh  = smem + 72;       // [144]
    float* sWoutY= smem + 216;      // [36]
    float* sbias = smem + 252;      // [8]
    float* sWin  = smem + 260;      // [9]
    float* sbin  = smem + 269;
    float* sbout = smem + 270;      // [2]
    float* sred  = smem + 272;      // [16]
    float* sx    = smem + 288;      // [36*68] x, offset (-2,-2)
    float* szi   = smem + 2736;     // [34*66] zi, offset (-1,-1)
    float* shp   = smem + 4980;     // [2][2][34*66] h: [buf][ch]

    const int tid = threadIdx.x;
    const int bx  = blockIdx.x;              // rank in cluster (0..7)
    const int b   = blockIdx.y;              // image
    const int tx  = bx & 1, ty = bx >> 1;    // tile coords (2 x 4)
    const int gx0 = tx * TW, gy0 = ty * TH;
    const int ix = tid & 63;                 // column within tile
    const int yg = (tid >> 6) << 3;          // first of 8 rows handled
    const unsigned shp_u32 = smem_u32(shp);

    // ---- weights -> smem (once) ----
    if (tid < 144) sWhh[tid] = Whh[tid];
    if (tid < 72)  sWih[tid] = Wih[tid];
    if (tid < 36) {  // Wout_y = Wout[:,:,:2,:], src flat (k*4+ci)*2+co
        int k = tid >> 2, ci = (tid >> 1) & 1, co = tid & 1;
        sWoutY[tid] = Wout[(k * 4 + ci) * 2 + co];
    }
    if (tid < 9) sWin[tid] = Win[tid];
    if (tid < 8) sbias[tid] = b_ih[tid] + b_hh[tid];
    if (tid < 2) sbout[tid] = b_out[tid];
    if (tid == 0) sbin[0] = b_in[0];
    for (int i = tid; i < 4 * EXN; i += 256) shp[i] = 0.0f;   // h_0 = 0

    float c0[8], c1[8];
    #pragma unroll
    for (int k = 0; k < 8; k++) { c0[k] = 0.0f; c1[k] = 0.0f; }

    // ---- prologue: x(0), zi(0), channel-0 log-prob ----
    {
        const float* xin = x + (size_t)(b * Cn) * HW;
        for (int i = tid; i < SXH * SXW; i += 256) {
            int r = i / SXW, c = i - r * SXW;
            int gy = gy0 - 2 + r, gx = gx0 - 2 + c;
            float v = 0.0f;
            if ((unsigned)gy < Hn && (unsigned)gx < Wn) v = xin[gy * Wn + gx];
            sx[i] = v;
        }
    }
    __syncthreads();

    const u64* w1p = (const u64*)sWih;
    const u64* w2p = (const u64*)sWhh;
    const u64* wop = (const u64*)sWoutY;
    const u64* sbp = (const u64*)sbias;
    const u64 pbias = pack2f(sbout[0], sbout[1]);

    float lpacc = 0.0f;
    {
        float mu = sbout[0], ls = sbout[1];
        float e = __expf(-ls);
        #pragma unroll
        for (int k = 0; k < 8; k++) {
            float xv = sx[(yg + k + 2) * SXW + ix + 2];
            float z = (xv - mu) * e;
            lpacc += -0.5f * z * z - ls - 0.9189385332046727f;
        }
    }
    {
        float bin = sbin[0];
        for (int i = tid; i < EXN; i += 256) {
            int r = i / EXW, c = i - r * EXW;
            int gy = gy0 - 1 + r, gx = gx0 - 1 + c;
            float v = 0.0f;
            if ((unsigned)gy < Hn && (unsigned)gx < Wn) {
                v = bin;
                #pragma unroll
                for (int dy = 0; dy < 3; dy++)
                    #pragma unroll
                    for (int dx = 0; dx < 3; dx++)
                        v += sx[(r + dy) * SXW + (c + dx)] * sWin[dy * 3 + dx];
            }
            szi[i] = v;
        }
    }
    __syncthreads();
    // All CTAs' smem zeroing must complete before any step-0 remote push.
    asm volatile("barrier.cluster.arrive.aligned;" ::: "memory");
    asm volatile("barrier.cluster.wait.aligned;" ::: "memory");

    for (int t = 0; t < 15; t++) {
        const int cur = t & 1, nxt = cur ^ 1;
        float* sh0  = shp + cur * 2 * EXN;
        float* sh1  = sh0 + EXN;
        float* shn0 = shp + nxt * 2 * EXN;
        float* shn1 = shn0 + EXN;
        const unsigned shn0_u32 = shp_u32 + (unsigned)(nxt * 2 * EXN) * 4u;

        // (1) gates + LSTM, interior, tap-outer in 2 passes of 4 rows.
        //     Border h pixels are pushed into neighbor CTAs' smem halos.
        #pragma unroll
        for (int p = 0; p < 2; p++) {
            u64 acc[4][4];
            #pragma unroll
            for (int j = 0; j < 4; j++) {
                acc[j][0] = sbp[0]; acc[j][1] = sbp[1];
                acc[j][2] = sbp[2]; acc[j][3] = sbp[3];
            }
            #pragma unroll
            for (int tap = 0; tap < 9; tap++) {
                const int dy = tap / 3, dx = tap % 3;
                u64 wz0 = w1p[tap * 4 + 0], wz1 = w1p[tap * 4 + 1];
                u64 wz2 = w1p[tap * 4 + 2], wz3 = w1p[tap * 4 + 3];
                u64 wa0 = w2p[tap * 8 + 0], wa1 = w2p[tap * 8 + 1];
                u64 wa2 = w2p[tap * 8 + 2], wa3 = w2p[tap * 8 + 3];
                u64 wb0 = w2p[tap * 8 + 4], wb1 = w2p[tap * 8 + 5];
                u64 wb2 = w2p[tap * 8 + 6], wb3 = w2p[tap * 8 + 7];
                #pragma unroll
                for (int j = 0; j < 4; j++) {
                    int si = (yg + p * 4 + j + dy) * EXW + ix + dx;
                    u64 zp  = pack2(szi[si]);
                    u64 h0p = pack2(sh0[si]);
                    u64 h1p = pack2(sh1[si]);
                    acc[j][0] = ffma2(zp,  wz0, acc[j][0]);
                    acc[j][1] = ffma2(zp,  wz1, acc[j][1]);
                    acc[j][2] = ffma2(zp,  wz2, acc[j][2]);
                    acc[j][3] = ffma2(zp,  wz3, acc[j][3]);
                    acc[j][0] = ffma2(h0p, wa0, acc[j][0]);
                    acc[j][1] = ffma2(h0p, wa1, acc[j][1]);
                    acc[j][2] = ffma2(h0p, wa2, acc[j][2]);
                    acc[j][3] = ffma2(h0p, wa3, acc[j][3]);
                    acc[j][0] = ffma2(h1p, wb0, acc[j][0]);
                    acc[j][1] = ffma2(h1p, wb1, acc[j][1]);
                    acc[j][2] = ffma2(h1p, wb2, acc[j][2]);
                    acc[j][3] = ffma2(h1p, wb3, acc[j][3]);
                }
            }
            #pragma unroll
            for (int j = 0; j < 4; j++) {
                const int k = p * 4 + j;
                int R = yg + k;
                float i0, i1, g0, g1, f0, f1, o0, o1;
                unpack2(acc[j][0], i0, i1); unpack2(acc[j][1], g0, g1);
                unpack2(acc[j][2], f0, f1); unpack2(acc[j][3], o0, o1);
                float cn0 = sigm(f0 + 1.0f) * c0[k] + sigm(i0) * tanh_fast(g0);
                float cn1 = sigm(f1 + 1.0f) * c1[k] + sigm(i1) * tanh_fast(g1);
                c0[k] = cn0; c1[k] = cn1;
                float hn0 = sigm(o0) * tanh_fast(cn0);
                float hn1 = sigm(o1) * tanh_fast(cn1);
                int ei = (R + 1) * EXW + ix + 1;
                shn0[ei] = hn0; shn1[ei] = hn1;
                // remote halo pushes
                #define PUSH_H(rank, rr, cc) do { \
                    unsigned a_ = mapa32(shn0_u32 + (unsigned)((rr) * EXW + (cc)) * 4u, (unsigned)(rank)); \
                    st_cluster(a_, hn0); \
                    st_cluster(a_ + (unsigned)EXN * 4u, hn1); \
                } while (0)
                if (ix == 0 && tx == 1) {
                    PUSH_H(bx - 1, R + 1, EXW - 1);
                    if (R == 0 && ty > 0)      PUSH_H(bx - 3, EXH - 1, EXW - 1);
                    if (R == TH - 1 && ty < 3) PUSH_H(bx + 1, 0, EXW - 1);
                }
                if (ix == TW - 1 && tx == 0) {
                    PUSH_H(bx + 1, R + 1, 0);
                    if (R == 0 && ty > 0)      PUSH_H(bx - 1, EXH - 1, 0);
                    if (R == TH - 1 && ty < 3) PUSH_H(bx + 3, 0, 0);
                }
                if (R == 0 && ty > 0)      PUSH_H(bx - 2, EXH - 1, ix + 1);
                if (R == TH - 1 && ty < 3) PUSH_H(bx + 2, 0, ix + 1);
                #undef PUSH_H
            }
        }
        // (2) release-arrive: our h(t+1) interior + pushes are published
        asm volatile("barrier.cluster.arrive.aligned;" ::: "memory");
        __syncthreads();
        // (3) load x(t+1) (hides cluster skew)
        {
            const float* xin = x + (size_t)(b * Cn + t + 1) * HW;
            for (int i = tid; i < SXH * SXW; i += 256) {
                int r = i / SXW, c = i - r * SXW;
                int gy = gy0 - 2 + r, gx = gx0 - 2 + c;
                float v = 0.0f;
                if ((unsigned)gy < Hn && (unsigned)gx < Wn) v = xin[gy * Wn + gx];
                sx[i] = v;
            }
        }
        __syncthreads();
        // (4) zi(t+1) (hides cluster skew; zi(t) fully consumed in phase 1)
        if (t < 14) {
            float bin = sbin[0];
            for (int i = tid; i < EXN; i += 256) {
                int r = i / EXW, c = i - r * EXW;
                int gy = gy0 - 1 + r, gx = gx0 - 1 + c;
                float v = 0.0f;
                if ((unsigned)gy < Hn && (unsigned)gx < Wn) {
                    v = bin;
                    #pragma unroll
                    for (int dy = 0; dy < 3; dy++)
                        #pragma unroll
                        for (int dx = 0; dx < 3; dx++)
                            v += sx[(r + dy) * SXW + (c + dx)] * sWin[dy * 3 + dx];
                }
                szi[i] = v;
            }
        }
        // (5) acquire-wait: all CTAs' h(t+1) pushes have landed in our halo
        asm volatile("barrier.cluster.wait.aligned;" ::: "memory");
        __syncthreads();
        // (6) out conv over h(t+1) ext; log-prob vs x(t+1) (in sx)
        #pragma unroll
        for (int k = 0; k < 8; k++) {
            int R = yg + k;
            u64 pp = pbias;
            #pragma unroll
            for (int tap = 0; tap < 9; tap++) {
                const int dy = tap / 3, dx = tap % 3;
                int si = (R + dy) * EXW + ix + dx;
                pp = ffma2(pack2(shn0[si]), wop[tap * 2 + 0], pp);
                pp = ffma2(pack2(shn1[si]), wop[tap * 2 + 1], pp);
            }
            float p0, p1;
            unpack2(pp, p0, p1);
            float xv = sx[(R + 2) * SXW + ix + 2];
            float e = __expf(-p1);
            float z = (xv - p0) * e;
            lpacc += -0.5f * z * z - p1 - 0.9189385332046727f;
        }
    }

    float tot = block_sum256(lpacc, sred);
    if (tid == 0) atomicAdd(&out[b], tot);
}

extern "C" void kernel_launch(void* const* d_in, const int* in_sizes, int n_in,
                              void* d_out, int out_size) {
    const float* x     = (const float*)d_in[0];
    const float* Win   = (const float*)d_in[1];
    const float* b_in  = (const float*)d_in[2];
    const float* Wih   = (const float*)d_in[3];
    const float* b_ih  = (const float*)d_in[4];
    const float* Whh   = (const float*)d_in[5];
    const float* b_hh  = (const float*)d_in[6];
    const float* Wout  = (const float*)d_in[7];
    const float* b_out = (const float*)d_in[8];
    float* out = (float*)d_out;

    static int smem_set = 0;
    const int smem_bytes = (4980 + 4 * EXN) * 4;   // 55824 B
    if (!smem_set) {
        cudaFuncSetAttribute(lstm_kernel,
                             cudaFuncAttributeMaxDynamicSharedMemorySize,
                             smem_bytes);
        smem_set = 1;
    }

    zero_out_kernel<<<1, 32>>>(out);

    dim3 grid(8, Bn, 1);   // cluster (8,1,1) = one image; 32 clusters
    lstm_kernel<<<grid, 256, smem_bytes>>>(x, Win, b_in, Wih, b_ih, Whh, b_hh,
                                           Wout, b_out, out);
}

// round 9
// speedup vs baseline: 2.0072x; 1.0045x over previous
#include <cuda_runtime.h>
#include <math.h>

#define Bn 32
#define Cn 16
#define Hn 128
#define Wn 128
#define HW (Hn * Wn)
#define TW 64          // tile width
#define TH 32          // tile height; 2x4 = 8 tiles per image = one cluster
#define EXW 66         // extended (+-1)
#define EXH 34
#define SXW 68         // x tile (+-2)
#define SXH 36
#define EXN (EXH * EXW)   // 2244

typedef unsigned long long u64;

__device__ __forceinline__ u64 ffma2(u64 a, u64 b, u64 c) {
    u64 d;
    asm("fma.rn.f32x2 %0, %1, %2, %3;" : "=l"(d) : "l"(a), "l"(b), "l"(c));
    return d;
}
__device__ __forceinline__ u64 pack2(float v) {
    u64 r;
    asm("mov.b64 %0, {%1, %1};" : "=l"(r) : "f"(v));
    return r;
}
__device__ __forceinline__ u64 pack2f(float a, float b) {
    u64 r;
    asm("mov.b64 %0, {%1, %2};" : "=l"(r) : "f"(a), "f"(b));
    return r;
}
__device__ __forceinline__ void unpack2(u64 v, float& lo, float& hi) {
    asm("mov.b64 {%0, %1}, %2;" : "=f"(lo), "=f"(hi) : "l"(v));
}
__device__ __forceinline__ float tanh_fast(float x) {
    float y;
    asm("tanh.approx.f32 %0, %1;" : "=f"(y) : "f"(x));
    return y;
}
__device__ __forceinline__ float sigm(float v) {
    return fmaf(tanh_fast(0.5f * v), 0.5f, 0.5f);
}
__device__ __forceinline__ unsigned smem_u32(const void* p) {
    unsigned a;
    asm("{ .reg .u64 t; cvta.to.shared.u64 t, %1; cvt.u32.u64 %0, t; }"
        : "=r"(a) : "l"(p));
    return a;
}
__device__ __forceinline__ unsigned mapa32(unsigned addr, unsigned rank) {
    unsigned r;
    asm("mapa.shared::cluster.u32 %0, %1, %2;" : "=r"(r) : "r"(addr), "r"(rank));
    return r;
}
__device__ __forceinline__ void st_cluster(unsigned addr, float v) {
    asm volatile("st.shared::cluster.f32 [%0], %1;" :: "r"(addr), "f"(v) : "memory");
}

__device__ __forceinline__ float block_sum256(float v, float* sred) {
    #pragma unroll
    for (int o = 16; o > 0; o >>= 1) v += __shfl_down_sync(0xffffffffu, v, o);
    int lane = threadIdx.x & 31, wid = threadIdx.x >> 5;
    if (lane == 0) sred[wid] = v;
    __syncthreads();
    if (wid == 0) {
        v = (lane < 8) ? sred[lane] : 0.0f;
        #pragma unroll
        for (int o = 4; o > 0; o >>= 1) v += __shfl_down_sync(0xffffffffu, v, o);
    }
    return v;  // valid in thread 0
}

__global__ void zero_out_kernel(float* out) {
    if (threadIdx.x < Bn) out[threadIdx.x] = 0.0f;
}

// Persistent fused ConvLSTM. Cluster (8 CTAs) = one image, CTA = 64x32 tile.
// h state lives in smem (double-buffered). Border h pixels are pushed straight
// into neighbors' smem halos via st.shared::cluster; per-step sync is a split
// cluster barrier (arrive after gates, wait before halo reads), with x(t+1)
// load + zi(t+1) hiding the skew. Out-conv uses a dx-outer rotation: each
// loaded h-pair feeds 3 row-accumulators, weights hoisted per column.
__global__ __launch_bounds__(256, 2) __cluster_dims__(8, 1, 1)
void lstm_kernel(
    const float* __restrict__ x,
    const float* __restrict__ Win,  const float* __restrict__ b_in,
    const float* __restrict__ Wih,  const float* __restrict__ b_ih,
    const float* __restrict__ Whh,  const float* __restrict__ b_hh,
    const float* __restrict__ Wout, const float* __restrict__ b_out,
    float* __restrict__ out)
{
    extern __shared__ __align__(16) float smem[];
    float* sWih  = smem;            // [72]
    float* sWhh  = smem + 72;       // [144]
    float* sWoutY= smem + 216;      // [36]
    float* sbias = smem + 252;      // [8]
    float* sWin  = smem + 260;      // [9]
    float* sbin  = smem + 269;
    float* sbout = smem + 270;      // [2]
    float* sred  = smem + 272;      // [16]
    float* sx    = smem + 288;      // [36*68] x, offset (-2,-2)
    float* szi   = smem + 2736;     // [34*66] zi, offset (-1,-1)
    float* shp   = smem + 4980;     // [2][2][34*66] h: [buf][ch]

    const int tid = threadIdx.x;
    const int bx  = blockIdx.x;              // rank in cluster (0..7)
    const int b   = blockIdx.y;              // image
    const int tx  = bx & 1, ty = bx >> 1;    // tile coords (2 x 4)
    const int gx0 = tx * TW, gy0 = ty * TH;
    const int ix = tid & 63;                 // column within tile
    const int yg = (tid >> 6) << 3;          // first of 8 rows handled
    const unsigned shp_u32 = smem_u32(shp);

    // ---- weights -> smem (once) ----
    if (tid < 144) sWhh[tid] = Whh[tid];
    if (tid < 72)  sWih[tid] = Wih[tid];
    if (tid < 36) {  // Wout_y = Wout[:,:,:2,:], src flat (k*4+ci)*2+co
        int k = tid >> 2, ci = (tid >> 1) & 1, co = tid & 1;
        sWoutY[tid] = Wout[(k * 4 + ci) * 2 + co];
    }
    if (tid < 9) sWin[tid] = Win[tid];
    if (tid < 8) sbias[tid] = b_ih[tid] + b_hh[tid];
    if (tid < 2) sbout[tid] = b_out[tid];
    if (tid == 0) sbin[0] = b_in[0];
    for (int i = tid; i < 4 * EXN; i += 256) shp[i] = 0.0f;   // h_0 = 0

    float c0[8], c1[8];
    #pragma unroll
    for (int k = 0; k < 8; k++) { c0[k] = 0.0f; c1[k] = 0.0f; }

    // ---- prologue: x(0), zi(0), channel-0 log-prob ----
    {
        const float* xin = x + (size_t)(b * Cn) * HW;
        for (int i = tid; i < SXH * SXW; i += 256) {
            int r = i / SXW, c = i - r * SXW;
            int gy = gy0 - 2 + r, gx = gx0 - 2 + c;
            float v = 0.0f;
            if ((unsigned)gy < Hn && (unsigned)gx < Wn) v = xin[gy * Wn + gx];
            sx[i] = v;
        }
    }
    __syncthreads();

    const u64* w1p = (const u64*)sWih;
    const u64* w2p = (const u64*)sWhh;
    const u64* wop = (const u64*)sWoutY;
    const u64* sbp = (const u64*)sbias;
    const u64 pbias = pack2f(sbout[0], sbout[1]);

    float lpacc = 0.0f;
    {
        float mu = sbout[0], ls = sbout[1];
        float e = __expf(-ls);
        #pragma unroll
        for (int k = 0; k < 8; k++) {
            float xv = sx[(yg + k + 2) * SXW + ix + 2];
            float z = (xv - mu) * e;
            lpacc += -0.5f * z * z - ls - 0.9189385332046727f;
        }
    }
    {
        float bin = sbin[0];
        for (int i = tid; i < EXN; i += 256) {
            int r = i / EXW, c = i - r * EXW;
            int gy = gy0 - 1 + r, gx = gx0 - 1 + c;
            float v = 0.0f;
            if ((unsigned)gy < Hn && (unsigned)gx < Wn) {
                v = bin;
                #pragma unroll
                for (int dy = 0; dy < 3; dy++)
                    #pragma unroll
                    for (int dx = 0; dx < 3; dx++)
                        v += sx[(r + dy) * SXW + (c + dx)] * sWin[dy * 3 + dx];
            }
            szi[i] = v;
        }
    }
    __syncthreads();
    // All CTAs' smem zeroing must complete before any step-0 remote push.
    asm volatile("barrier.cluster.arrive.aligned;" ::: "memory");
    asm volatile("barrier.cluster.wait.aligned;" ::: "memory");

    for (int t = 0; t < 15; t++) {
        const int cur = t & 1, nxt = cur ^ 1;
        float* sh0  = shp + cur * 2 * EXN;
        float* sh1  = sh0 + EXN;
        float* shn0 = shp + nxt * 2 * EXN;
        float* shn1 = shn0 + EXN;
        const unsigned shn0_u32 = shp_u32 + (unsigned)(nxt * 2 * EXN) * 4u;

        // (1) gates + LSTM, interior, tap-outer in 2 passes of 4 rows.
        //     Border h pixels are pushed into neighbor CTAs' smem halos.
        #pragma unroll
        for (int p = 0; p < 2; p++) {
            u64 acc[4][4];
            #pragma unroll
            for (int j = 0; j < 4; j++) {
                acc[j][0] = sbp[0]; acc[j][1] = sbp[1];
                acc[j][2] = sbp[2]; acc[j][3] = sbp[3];
            }
            #pragma unroll
            for (int tap = 0; tap < 9; tap++) {
                const int dy = tap / 3, dx = tap % 3;
                u64 wz0 = w1p[tap * 4 + 0], wz1 = w1p[tap * 4 + 1];
                u64 wz2 = w1p[tap * 4 + 2], wz3 = w1p[tap * 4 + 3];
                u64 wa0 = w2p[tap * 8 + 0], wa1 = w2p[tap * 8 + 1];
                u64 wa2 = w2p[tap * 8 + 2], wa3 = w2p[tap * 8 + 3];
                u64 wb0 = w2p[tap * 8 + 4], wb1 = w2p[tap * 8 + 5];
                u64 wb2 = w2p[tap * 8 + 6], wb3 = w2p[tap * 8 + 7];
                #pragma unroll
                for (int j = 0; j < 4; j++) {
                    int si = (yg + p * 4 + j + dy) * EXW + ix + dx;
                    u64 zp  = pack2(szi[si]);
                    u64 h0p = pack2(sh0[si]);
                    u64 h1p = pack2(sh1[si]);
                    acc[j][0] = ffma2(zp,  wz0, acc[j][0]);
                    acc[j][1] = ffma2(zp,  wz1, acc[j][1]);
                    acc[j][2] = ffma2(zp,  wz2, acc[j][2]);
                    acc[j][3] = ffma2(zp,  wz3, acc[j][3]);
                    acc[j][0] = ffma2(h0p, wa0, acc[j][0]);
                    acc[j][1] = ffma2(h0p, wa1, acc[j][1]);
                    acc[j][2] = ffma2(h0p, wa2, acc[j][2]);
                    acc[j][3] = ffma2(h0p, wa3, acc[j][3]);
                    acc[j][0] = ffma2(h1p, wb0, acc[j][0]);
                    acc[j][1] = ffma2(h1p, wb1, acc[j][1]);
                    acc[j][2] = ffma2(h1p, wb2, acc[j][2]);
                    acc[j][3] = ffma2(h1p, wb3, acc[j][3]);
                }
            }
            #pragma unroll
            for (int j = 0; j < 4; j++) {
                const int k = p * 4 + j;
                int R = yg + k;
                float i0, i1, g0, g1, f0, f1, o0, o1;
                unpack2(acc[j][0], i0, i1); unpack2(acc[j][1], g0, g1);
                unpack2(acc[j][2], f0, f1); unpack2(acc[j][3], o0, o1);
                float cn0 = sigm(f0 + 1.0f) * c0[k] + sigm(i0) * tanh_fast(g0);
                float cn1 = sigm(f1 + 1.0f) * c1[k] + sigm(i1) * tanh_fast(g1);
                c0[k] = cn0; c1[k] = cn1;
                float hn0 = sigm(o0) * tanh_fast(cn0);
                float hn1 = sigm(o1) * tanh_fast(cn1);
                int ei = (R + 1) * EXW + ix + 1;
                shn0[ei] = hn0; shn1[ei] = hn1;
                // remote halo pushes
                #define PUSH_H(rank, rr, cc) do { \
                    unsigned a_ = mapa32(shn0_u32 + (unsigned)((rr) * EXW + (cc)) * 4u, (unsigned)(rank)); \
                    st_cluster(a_, hn0); \
                    st_cluster(a_ + (unsigned)EXN * 4u, hn1); \
                } while (0)
                if (ix == 0 && tx == 1) {
                    PUSH_H(bx - 1, R + 1, EXW - 1);
                    if (R == 0 && ty > 0)      PUSH_H(bx - 3, EXH - 1, EXW - 1);
                    if (R == TH - 1 && ty < 3) PUSH_H(bx + 1, 0, EXW - 1);
                }
                if (ix == TW - 1 && tx == 0) {
                    PUSH_H(bx + 1, R + 1, 0);
                    if (R == 0 && ty > 0)      PUSH_H(bx - 1, EXH - 1, 0);
                    if (R == TH - 1 && ty < 3) PUSH_H(bx + 3, 0, 0);
                }
                if (R == 0 && ty > 0)      PUSH_H(bx - 2, EXH - 1, ix + 1);
                if (R == TH - 1 && ty < 3) PUSH_H(bx + 2, 0, ix + 1);
                #undef PUSH_H
            }
        }
        // (2) release-arrive: our h(t+1) interior + pushes are published
        asm volatile("barrier.cluster.arrive.aligned;" ::: "memory");
        __syncthreads();
        // (3) load x(t+1) (hides cluster skew)
        {
            const float* xin = x + (size_t)(b * Cn + t + 1) * HW;
            for (int i = tid; i < SXH * SXW; i += 256) {
                int r = i / SXW, c = i - r * SXW;
                int gy = gy0 - 2 + r, gx = gx0 - 2 + c;
                float v = 0.0f;
                if ((unsigned)gy < Hn && (unsigned)gx < Wn) v = xin[gy * Wn + gx];
                sx[i] = v;
            }
        }
        __syncthreads();
        // (4) zi(t+1) (hides cluster skew; zi(t) fully consumed in phase 1)
        if (t < 14) {
            float bin = sbin[0];
            for (int i = tid; i < EXN; i += 256) {
                int r = i / EXW, c = i - r * EXW;
                int gy = gy0 - 1 + r, gx = gx0 - 1 + c;
                float v = 0.0f;
                if ((unsigned)gy < Hn && (unsigned)gx < Wn) {
                    v = bin;
                    #pragma unroll
                    for (int dy = 0; dy < 3; dy++)
                        #pragma unroll
                        for (int dx = 0; dx < 3; dx++)
                            v += sx[(r + dy) * SXW + (c + dx)] * sWin[dy * 3 + dx];
                }
                szi[i] = v;
            }
        }
        // (5) acquire-wait: all CTAs' h(t+1) pushes have landed in our halo
        asm volatile("barrier.cluster.wait.aligned;" ::: "memory");
        __syncthreads();
        // (6) out conv over h(t+1) ext, dx-outer rotation: 10-row sweep per
        //     column, each loaded h-pair feeds up to 3 row-accumulators.
        {
            u64 pp[8];
            #pragma unroll
            for (int k = 0; k < 8; k++) pp[k] = pbias;
            #pragma unroll
            for (int dx = 0; dx < 3; dx++) {
                u64 w00 = wop[(0 * 3 + dx) * 2 + 0], w01 = wop[(0 * 3 + dx) * 2 + 1];
                u64 w10 = wop[(1 * 3 + dx) * 2 + 0], w11 = wop[(1 * 3 + dx) * 2 + 1];
                u64 w20 = wop[(2 * 3 + dx) * 2 + 0], w21 = wop[(2 * 3 + dx) * 2 + 1];
                #pragma unroll
                for (int rr = 0; rr < 10; rr++) {
                    int si = (yg + rr) * EXW + ix + dx;
                    u64 h0 = pack2(shn0[si]);
                    u64 h1 = pack2(shn1[si]);
                    if (rr < 8) {
                        pp[rr] = ffma2(h0, w00, pp[rr]);
                        pp[rr] = ffma2(h1, w01, pp[rr]);
                    }
                    if (rr >= 1 && rr < 9) {
                        pp[rr - 1] = ffma2(h0, w10, pp[rr - 1]);
                        pp[rr - 1] = ffma2(h1, w11, pp[rr - 1]);
                    }
                    if (rr >= 2) {
                        pp[rr - 2] = ffma2(h0, w20, pp[rr - 2]);
                        pp[rr - 2] = ffma2(h1, w21, pp[rr - 2]);
                    }
                }
            }
            #pragma unroll
            for (int k = 0; k < 8; k++) {
                float p0, p1;
                unpack2(pp[k], p0, p1);
                float xv = sx[(yg + k + 2) * SXW + ix + 2];
                float e = __expf(-p1);
                float z = (xv - p0) * e;
                lpacc += -0.5f * z * z - p1 - 0.9189385332046727f;
            }
        }
    }

    float tot = block_sum256(lpacc, sred);
    if (tid == 0) atomicAdd(&out[b], tot);
}

extern "C" void kernel_launch(void* const* d_in, const int* in_sizes, int n_in,
                              void* d_out, int out_size) {
    const float* x     = (const float*)d_in[0];
    const float* Win   = (const float*)d_in[1];
    const float* b_in  = (const float*)d_in[2];
    const float* Wih   = (const float*)d_in[3];
    const float* b_ih  = (const float*)d_in[4];
    const float* Whh   = (const float*)d_in[5];
    const float* b_hh  = (const float*)d_in[6];
    const float* Wout  = (const float*)d_in[7];
    const float* b_out = (const float*)d_in[8];
    float* out = (float*)d_out;

    static int smem_set = 0;
    const int smem_bytes = (4980 + 4 * EXN) * 4;   // 55824 B
    if (!smem_set) {
        cudaFuncSetAttribute(lstm_kernel,
                             cudaFuncAttributeMaxDynamicSharedMemorySize,
                             smem_bytes);
        smem_set = 1;
    }

    zero_out_kernel<<<1, 32>>>(out);

    dim3 grid(8, Bn, 1);   // cluster (8,1,1) = one image; 32 clusters
    lstm_kernel<<<grid, 256, smem_bytes>>>(x, Win, b_in, Wih, b_ih, Whh, b_hh,
                                           Wout, b_out, out);
}